// round 15
// baseline (speedup 1.0000x reference)
#include <cuda_runtime.h>

#define Bc   4
#define Hc   512
#define Wc   229
#define Cc   32
#define OUTc 88
#define FRAME_ELEMS (Bc*Hc*OUTc)     /* 180224 */
#define NROW (Bc*Hc)                 /* 2048 */
#define NOT  6                       /* out tiles of 16 (88 -> 96 padded) */
#define WTIL (Wc*16)                 /* 3664 floats per out-tile */
#define PRTS 20                      /* partial row stride (floats) */
#define NKS  8                       /* k2 K splits (one per warp) */

__device__ __align__(16) float g_ovT[Wc*NROW];      // ov transposed [w][row]
__device__ __align__(16) float g_w16[NOT*WTIL];     // weights [ot][w][16], pads zero-init

// ---------------------------------------------------------------------------
// K1: 4 consecutive (b,h) rows per block (512 blocks x 256 thr).
// Softmax per row (MUFU __expf); attn staged -> contiguous coalesced
// writeback; ov written transposed as ONE float4 per thread.
// Blocks 0..87 fold one WeffT column into g_w16.
// ---------------------------------------------------------------------------
__global__ void __launch_bounds__(256)
k1(const float* __restrict__ spec,
   const float* __restrict__ Wq,  const float* __restrict__ Wk,
   const float* __restrict__ Wv,  const float* __restrict__ rel_t,
   const float* __restrict__ rel_f, const float* __restrict__ W_lin,
   float* __restrict__ out_attn)
{
    __shared__ __align__(16) float sh[6*232];        // 6 halo rows
    __shared__ __align__(16) float s_attn[4*Wc*9];   // 4 rows of attn (8244 f)
    __shared__ float s_scal[7];

    int blk  = blockIdx.x;                   // 0..511
    int b    = blk >> 7;                     // batch
    int h0   = (blk & 127) * 4;              // first h of quad
    int row0 = blk * 4;                      // global row
    int t    = threadIdx.x;

    if (t < 7) {
        if (t == 0) {
            float a = 0.f;
            #pragma unroll
            for (int c = 0; c < Cc; c++) a = fmaf(Wq[c], Wk[c], a);
            s_scal[0] = a;
        } else if (t <= 3) {
            int kt = t - 1; float r = 0.f;
            #pragma unroll
            for (int c = 0; c < 16; c++) r = fmaf(Wq[c], rel_t[c*3 + kt], r);
            s_scal[t] = r;
        } else {
            int kf = t - 4; float r = 0.f;
            #pragma unroll
            for (int c = 0; c < 16; c++) r = fmaf(Wq[16 + c], rel_f[c*3 + kf], r);
            s_scal[t] = r;
        }
    }

    // halo: rows h0-1 .. h0+4, cols -1..230
    for (int i = t; i < 6*232; i += 256) {
        int j  = i / 232;
        int cc = i - j*232;
        int w  = cc - 1;
        int gh = h0 - 1 + j;
        float v = 0.f;
        if (gh >= 0 && gh < Hc && w >= 0 && w < Wc)
            v = spec[(b*Hc + gh)*Wc + w];
        sh[j*232 + cc] = v;
    }
    __syncthreads();

    if (t < Wc) {
        const float A = s_scal[0];
        const float Rt[3] = { s_scal[1], s_scal[2], s_scal[3] };
        const float Rf[3] = { s_scal[4], s_scal[5], s_scal[6] };
        float ovv[4];

        #pragma unroll
        for (int r = 0; r < 4; r++) {
            const float* h0p = sh + (r    )*232 + t;   // w-1..w+1
            const float* h1p = sh + (r + 1)*232 + t;
            const float* h2p = sh + (r + 2)*232 + t;
            float s  = h1p[1];
            float sA = s * A;

            float nb[9], e[9];
            nb[0]=h0p[0]; nb[1]=h0p[1]; nb[2]=h0p[2];
            nb[3]=h1p[0]; nb[4]=h1p[1]; nb[5]=h1p[2];
            nb[6]=h2p[0]; nb[7]=h2p[1]; nb[8]=h2p[2];
            float sr0 = s*Rt[0], sr1 = s*Rt[1], sr2 = s*Rt[2];
            float sf0 = s*Rf[0], sf1 = s*Rf[1], sf2 = s*Rf[2];
            e[0]=fmaf(sA,nb[0],sr0+sf0); e[1]=fmaf(sA,nb[1],sr0+sf1); e[2]=fmaf(sA,nb[2],sr0+sf2);
            e[3]=fmaf(sA,nb[3],sr1+sf0); e[4]=fmaf(sA,nb[4],sr1+sf1); e[5]=fmaf(sA,nb[5],sr1+sf2);
            e[6]=fmaf(sA,nb[6],sr2+sf0); e[7]=fmaf(sA,nb[7],sr2+sf1); e[8]=fmaf(sA,nb[8],sr2+sf2);

            float m = e[0];
            #pragma unroll
            for (int k = 1; k < 9; k++) m = fmaxf(m, e[k]);
            float p[9], sum = 0.f;
            #pragma unroll
            for (int k = 0; k < 9; k++) { p[k] = __expf(e[k] - m); sum += p[k]; }
            float rinv = __fdividef(1.f, sum);

            float ov = 0.f;
            float* ap = s_attn + r*(Wc*9) + t*9;
            #pragma unroll
            for (int k = 0; k < 9; k++) {
                float a = p[k] * rinv;
                ap[k] = a;
                ov = fmaf(a, nb[k], ov);
            }
            ovv[r] = ov;
        }
        float4 o4 = { ovv[0], ovv[1], ovv[2], ovv[3] };
        *(float4*)&g_ovT[t*NROW + row0] = o4;
    }
    __syncthreads();

    float* dst = out_attn + (size_t)row0 * (Wc*9);
    for (int i = t; i < 4*Wc*9; i += 256)
        dst[i] = s_attn[i];

    if (blk < OUTc && t < Wc) {              // fold one Weff column -> g_w16
        const float* base = W_lin + blk*(Cc*Wc) + t;
        float acc = 0.f;
        #pragma unroll
        for (int c = 0; c < Cc; c++)
            acc = fmaf(base[c*Wc], Wv[c], acc);
        g_w16[(blk >> 4)*WTIL + t*16 + (blk & 15)] = acc;
    }
}

// ---------------------------------------------------------------------------
// helper: consume one 4-w group (16 FMA x 4) against smem weights
// ---------------------------------------------------------------------------
__device__ __forceinline__ void consume4(
    const float* __restrict__ s_w, int w,
    float v0, float v1, float v2, float v3,
    float4& a0, float4& a1, float4& a2, float4& a3)
{
    #pragma unroll
    for (int u = 0; u < 4; u++) {
        float v = (u == 0) ? v0 : (u == 1) ? v1 : (u == 2) ? v2 : v3;
        const float* wp = s_w + (w + u)*16;
        float4 q0 = *(const float4*)(wp     );
        float4 q1 = *(const float4*)(wp +  4);
        float4 q2 = *(const float4*)(wp +  8);
        float4 q3 = *(const float4*)(wp + 12);
        a0.x = fmaf(v, q0.x, a0.x); a0.y = fmaf(v, q0.y, a0.y);
        a0.z = fmaf(v, q0.z, a0.z); a0.w = fmaf(v, q0.w, a0.w);
        a1.x = fmaf(v, q1.x, a1.x); a1.y = fmaf(v, q1.y, a1.y);
        a1.z = fmaf(v, q1.z, a1.z); a1.w = fmaf(v, q1.w, a1.w);
        a2.x = fmaf(v, q2.x, a2.x); a2.y = fmaf(v, q2.y, a2.y);
        a2.z = fmaf(v, q2.z, a2.z); a2.w = fmaf(v, q2.w, a2.w);
        a3.x = fmaf(v, q3.x, a3.x); a3.y = fmaf(v, q3.y, a3.y);
        a3.z = fmaf(v, q3.z, a3.z); a3.w = fmaf(v, q3.w, a3.w);
    }
}

// ---------------------------------------------------------------------------
// K2: frame = sigmoid(ov @ Weff^T + b)
// grid (6 outTiles, 64 rowChunks) x 256 thr. Block: 32 rows x 16 outs.
// warp = K-chunk (8 of ~29), lane = row. SOFTWARE-PIPELINED ovT loads:
// group g+1's 4 LDGs issue BEFORE group g is consumed -> L2 latency hidden
// under 84 instrs/group x 4-5 warps/SMSP.
// ---------------------------------------------------------------------------
__global__ void __launch_bounds__(256)
k2(const float* __restrict__ b_lin, float* __restrict__ out_frame)
{
    __shared__ __align__(16) float s_w[WTIL];               // 14.6 KB
    __shared__ __align__(16) float s_prt[(NKS-1)*32*PRTS];  // 17.9 KB

    int t  = threadIdx.x;
    int ot = blockIdx.x;                     // out tile 0..5
    int rc = blockIdx.y;                     // row chunk 0..63

    {   // weight tile fill: contiguous float4 both sides
        const float4* src = (const float4*)(g_w16 + ot*WTIL);
        for (int i = t; i < WTIL/4; i += 256)
            ((float4*)s_w)[i] = src[i];
    }
    __syncthreads();

    int lane = t & 31;
    int ks   = t >> 5;                       // 0..7
    int row  = rc*32 + lane;
    int w0 = (ks * Wc) / NKS;
    int w1 = ((ks + 1) * Wc) / NKS;

    const float* ovcol = g_ovT + row;

    float4 a0 = {0,0,0,0}, a1 = {0,0,0,0}, a2 = {0,0,0,0}, a3 = {0,0,0,0};

    int ng = (w1 - w0) >> 2;                 // groups of 4 (7 typical)
    float v0, v1, v2, v3;
    if (ng > 0) {                            // prologue: load group 0
        v0 = __ldg(ovcol + (w0  )*NROW);
        v1 = __ldg(ovcol + (w0+1)*NROW);
        v2 = __ldg(ovcol + (w0+2)*NROW);
        v3 = __ldg(ovcol + (w0+3)*NROW);
    }
    for (int g = 0; g < ng; g++) {
        int w = w0 + g*4;
        float n0, n1, n2, n3;
        if (g + 1 < ng) {                    // prefetch group g+1 FIRST
            int wn = w + 4;
            n0 = __ldg(ovcol + (wn  )*NROW);
            n1 = __ldg(ovcol + (wn+1)*NROW);
            n2 = __ldg(ovcol + (wn+2)*NROW);
            n3 = __ldg(ovcol + (wn+3)*NROW);
        }
        consume4(s_w, w, v0, v1, v2, v3, a0, a1, a2, a3);
        if (g + 1 < ng) { v0 = n0; v1 = n1; v2 = n2; v3 = n3; }
    }
    for (int w = w0 + ng*4; w < w1; w++) {   // scalar tail (<=3)
        float v = __ldg(ovcol + w*NROW);
        const float* wp = s_w + w*16;
        float4 q0 = *(const float4*)(wp     );
        float4 q1 = *(const float4*)(wp +  4);
        float4 q2 = *(const float4*)(wp +  8);
        float4 q3 = *(const float4*)(wp + 12);
        a0.x = fmaf(v, q0.x, a0.x); a0.y = fmaf(v, q0.y, a0.y);
        a0.z = fmaf(v, q0.z, a0.z); a0.w = fmaf(v, q0.w, a0.w);
        a1.x = fmaf(v, q1.x, a1.x); a1.y = fmaf(v, q1.y, a1.y);
        a1.z = fmaf(v, q1.z, a1.z); a1.w = fmaf(v, q1.w, a1.w);
        a2.x = fmaf(v, q2.x, a2.x); a2.y = fmaf(v, q2.y, a2.y);
        a2.z = fmaf(v, q2.z, a2.z); a2.w = fmaf(v, q2.w, a2.w);
        a3.x = fmaf(v, q3.x, a3.x); a3.y = fmaf(v, q3.y, a3.y);
        a3.z = fmaf(v, q3.z, a3.z); a3.w = fmaf(v, q3.w, a3.w);
    }

    if (ks > 0) {                            // publish partials
        float* pp = s_prt + ((ks - 1)*32 + lane)*PRTS;
        *(float4*)(pp     ) = a0;  *(float4*)(pp +  4) = a1;
        *(float4*)(pp +  8) = a2;  *(float4*)(pp + 12) = a3;
    }
    __syncthreads();

    if (t < 32) {                            // warp 0: reduce + epilogue
        #pragma unroll
        for (int s = 0; s < NKS-1; s++) {
            const float* pp = s_prt + (s*32 + lane)*PRTS;
            float4 p0 = *(const float4*)(pp);
            float4 p1 = *(const float4*)(pp + 4);
            float4 p2 = *(const float4*)(pp + 8);
            float4 p3 = *(const float4*)(pp + 12);
            a0.x += p0.x; a0.y += p0.y; a0.z += p0.z; a0.w += p0.w;
            a1.x += p1.x; a1.y += p1.y; a1.z += p1.z; a1.w += p1.w;
            a2.x += p2.x; a2.y += p2.y; a2.z += p2.z; a2.w += p2.w;
            a3.x += p3.x; a3.y += p3.y; a3.z += p3.z; a3.w += p3.w;
        }

        int o0 = ot*16;
        float4 accs[4] = {a0, a1, a2, a3};
        #pragma unroll
        for (int g = 0; g < 4; g++) {
            int o = o0 + g*4;
            if (o < OUTc) {                  // 88 % 16 == 8: quads fully in/out
                float4 bb = *(const float4*)&b_lin[o];
                float4 rr;
                rr.x = __fdividef(1.f, 1.f + __expf(-(accs[g].x + bb.x)));
                rr.y = __fdividef(1.f, 1.f + __expf(-(accs[g].y + bb.y)));
                rr.z = __fdividef(1.f, 1.f + __expf(-(accs[g].z + bb.z)));
                rr.w = __fdividef(1.f, 1.f + __expf(-(accs[g].w + bb.w)));
                *(float4*)&out_frame[row*OUTc + o] = rr;
            }
        }
    }
}

// ---------------------------------------------------------------------------
extern "C" void kernel_launch(void* const* d_in, const int* in_sizes, int n_in,
                              void* d_out, int out_size)
{
    const float* spec  = (const float*)d_in[0];
    const float* Wq    = (const float*)d_in[1];
    const float* Wk    = (const float*)d_in[2];
    const float* Wv    = (const float*)d_in[3];
    const float* rel_t = (const float*)d_in[4];
    const float* rel_f = (const float*)d_in[5];
    const float* W_lin = (const float*)d_in[6];
    const float* b_lin = (const float*)d_in[7];
    float* out = (float*)d_out;

    k1<<<NROW/4, 256>>>(spec, Wq, Wk, Wv, rel_t, rel_f, W_lin, out + FRAME_ELEMS);
    dim3 g2(NOT, NROW/32);
    k2<<<g2, 256>>>(b_lin, out);
}

// round 16
// speedup vs baseline: 1.1218x; 1.1218x over previous
#include <cuda_runtime.h>

#define Bc   4
#define Hc   512
#define Wc   229
#define Cc   32
#define OUTc 88
#define FRAME_ELEMS (Bc*Hc*OUTc)     /* 180224 */
#define NROW (Bc*Hc)                 /* 2048 */
#define NOT  11                      /* out tiles of 8 (88 = 11*8 exact) */
#define WTIL (Wc*8)                  /* 1832 floats per out-tile */
#define PRTS 12                      /* partial row stride (48B, 16B-aligned) */
#define NKS  8                       /* k2 K splits (one per warp) */

__device__ __align__(16) float g_ovT[Wc*NROW];      // ov transposed [w][row]
__device__ __align__(16) float g_w8[NOT*WTIL];      // weights [ot][w][8]

// ---------------------------------------------------------------------------
// K1: 4 consecutive (b,h) rows per block (512 blocks x 256 thr).
// Softmax per row (MUFU __expf); attn staged -> contiguous coalesced
// writeback; ov written transposed as ONE float4 per thread.
// Blocks 0..87 fold one WeffT column into g_w8.
// ---------------------------------------------------------------------------
__global__ void __launch_bounds__(256)
k1(const float* __restrict__ spec,
   const float* __restrict__ Wq,  const float* __restrict__ Wk,
   const float* __restrict__ Wv,  const float* __restrict__ rel_t,
   const float* __restrict__ rel_f, const float* __restrict__ W_lin,
   float* __restrict__ out_attn)
{
    __shared__ __align__(16) float sh[6*232];        // 6 halo rows
    __shared__ __align__(16) float s_attn[4*Wc*9];   // 4 rows of attn (8244 f)
    __shared__ float s_scal[7];

    int blk  = blockIdx.x;                   // 0..511
    int b    = blk >> 7;                     // batch
    int h0   = (blk & 127) * 4;              // first h of quad
    int row0 = blk * 4;                      // global row
    int t    = threadIdx.x;

    if (t < 7) {
        if (t == 0) {
            float a = 0.f;
            #pragma unroll
            for (int c = 0; c < Cc; c++) a = fmaf(Wq[c], Wk[c], a);
            s_scal[0] = a;
        } else if (t <= 3) {
            int kt = t - 1; float r = 0.f;
            #pragma unroll
            for (int c = 0; c < 16; c++) r = fmaf(Wq[c], rel_t[c*3 + kt], r);
            s_scal[t] = r;
        } else {
            int kf = t - 4; float r = 0.f;
            #pragma unroll
            for (int c = 0; c < 16; c++) r = fmaf(Wq[16 + c], rel_f[c*3 + kf], r);
            s_scal[t] = r;
        }
    }

    // halo: rows h0-1 .. h0+4, cols -1..230
    for (int i = t; i < 6*232; i += 256) {
        int j  = i / 232;
        int cc = i - j*232;
        int w  = cc - 1;
        int gh = h0 - 1 + j;
        float v = 0.f;
        if (gh >= 0 && gh < Hc && w >= 0 && w < Wc)
            v = spec[(b*Hc + gh)*Wc + w];
        sh[j*232 + cc] = v;
    }
    __syncthreads();

    if (t < Wc) {
        const float A = s_scal[0];
        const float Rt[3] = { s_scal[1], s_scal[2], s_scal[3] };
        const float Rf[3] = { s_scal[4], s_scal[5], s_scal[6] };
        float ovv[4];

        #pragma unroll
        for (int r = 0; r < 4; r++) {
            const float* h0p = sh + (r    )*232 + t;   // w-1..w+1
            const float* h1p = sh + (r + 1)*232 + t;
            const float* h2p = sh + (r + 2)*232 + t;
            float s  = h1p[1];
            float sA = s * A;

            float nb[9], e[9];
            nb[0]=h0p[0]; nb[1]=h0p[1]; nb[2]=h0p[2];
            nb[3]=h1p[0]; nb[4]=h1p[1]; nb[5]=h1p[2];
            nb[6]=h2p[0]; nb[7]=h2p[1]; nb[8]=h2p[2];
            float sr0 = s*Rt[0], sr1 = s*Rt[1], sr2 = s*Rt[2];
            float sf0 = s*Rf[0], sf1 = s*Rf[1], sf2 = s*Rf[2];
            e[0]=fmaf(sA,nb[0],sr0+sf0); e[1]=fmaf(sA,nb[1],sr0+sf1); e[2]=fmaf(sA,nb[2],sr0+sf2);
            e[3]=fmaf(sA,nb[3],sr1+sf0); e[4]=fmaf(sA,nb[4],sr1+sf1); e[5]=fmaf(sA,nb[5],sr1+sf2);
            e[6]=fmaf(sA,nb[6],sr2+sf0); e[7]=fmaf(sA,nb[7],sr2+sf1); e[8]=fmaf(sA,nb[8],sr2+sf2);

            float m = e[0];
            #pragma unroll
            for (int k = 1; k < 9; k++) m = fmaxf(m, e[k]);
            float p[9], sum = 0.f;
            #pragma unroll
            for (int k = 0; k < 9; k++) { p[k] = __expf(e[k] - m); sum += p[k]; }
            float rinv = __fdividef(1.f, sum);

            float ov = 0.f;
            float* ap = s_attn + r*(Wc*9) + t*9;
            #pragma unroll
            for (int k = 0; k < 9; k++) {
                float a = p[k] * rinv;
                ap[k] = a;
                ov = fmaf(a, nb[k], ov);
            }
            ovv[r] = ov;
        }
        float4 o4 = { ovv[0], ovv[1], ovv[2], ovv[3] };
        *(float4*)&g_ovT[t*NROW + row0] = o4;
    }
    __syncthreads();

    float* dst = out_attn + (size_t)row0 * (Wc*9);
    for (int i = t; i < 4*Wc*9; i += 256)
        dst[i] = s_attn[i];

    if (blk < OUTc && t < Wc) {              // fold one Weff column -> g_w8
        const float* base = W_lin + blk*(Cc*Wc) + t;
        float acc = 0.f;
        #pragma unroll
        for (int c = 0; c < Cc; c++)
            acc = fmaf(base[c*Wc], Wv[c], acc);
        g_w8[(blk >> 3)*WTIL + t*8 + (blk & 7)] = acc;
    }
}

// ---------------------------------------------------------------------------
// helper: consume one 4-w group (8 FMA x 4) against smem weights
// ---------------------------------------------------------------------------
__device__ __forceinline__ void consume4(
    const float* __restrict__ s_w, int w,
    float v0, float v1, float v2, float v3,
    float4& a0, float4& a1)
{
    #pragma unroll
    for (int u = 0; u < 4; u++) {
        float v = (u == 0) ? v0 : (u == 1) ? v1 : (u == 2) ? v2 : v3;
        const float* wp = s_w + (w + u)*8;
        float4 q0 = *(const float4*)(wp    );
        float4 q1 = *(const float4*)(wp + 4);
        a0.x = fmaf(v, q0.x, a0.x); a0.y = fmaf(v, q0.y, a0.y);
        a0.z = fmaf(v, q0.z, a0.z); a0.w = fmaf(v, q0.w, a0.w);
        a1.x = fmaf(v, q1.x, a1.x); a1.y = fmaf(v, q1.y, a1.y);
        a1.z = fmaf(v, q1.z, a1.z); a1.w = fmaf(v, q1.w, a1.w);
    }
}

// ---------------------------------------------------------------------------
// K2: frame = sigmoid(ov @ Weff^T + b)
// grid (11 outTiles, 64 rowChunks) = 704 blocks x 256 thr -> ~38 warps/SM.
// Block: 32 rows x 8 outs. warp = K-chunk (8 of ~29), lane = row.
// Pipelined ovT LDGs; per w: 1 LDG + 2 broadcast LDS -> 8 FMA.
// ---------------------------------------------------------------------------
__global__ void __launch_bounds__(256)
k2(const float* __restrict__ b_lin, float* __restrict__ out_frame)
{
    __shared__ __align__(16) float s_w[WTIL];               // 7.3 KB
    __shared__ __align__(16) float s_prt[(NKS-1)*32*PRTS];  // 10.7 KB

    int t  = threadIdx.x;
    int ot = blockIdx.x;                     // out tile 0..10
    int rc = blockIdx.y;                     // row chunk 0..63

    {   // weight tile fill: contiguous float4 both sides
        const float4* src = (const float4*)(g_w8 + ot*WTIL);
        for (int i = t; i < WTIL/4; i += 256)
            ((float4*)s_w)[i] = src[i];
    }
    __syncthreads();

    int lane = t & 31;
    int ks   = t >> 5;                       // 0..7
    int row  = rc*32 + lane;
    int w0 = (ks * Wc) / NKS;
    int w1 = ((ks + 1) * Wc) / NKS;

    const float* ovcol = g_ovT + row;

    float4 a0 = {0,0,0,0}, a1 = {0,0,0,0};

    int ng = (w1 - w0) >> 2;                 // groups of 4 (7 typical)
    float v0, v1, v2, v3;
    if (ng > 0) {                            // prologue: load group 0
        v0 = __ldg(ovcol + (w0  )*NROW);
        v1 = __ldg(ovcol + (w0+1)*NROW);
        v2 = __ldg(ovcol + (w0+2)*NROW);
        v3 = __ldg(ovcol + (w0+3)*NROW);
    }
    for (int g = 0; g < ng; g++) {
        int w = w0 + g*4;
        float n0, n1, n2, n3;
        if (g + 1 < ng) {                    // prefetch group g+1 first
            int wn = w + 4;
            n0 = __ldg(ovcol + (wn  )*NROW);
            n1 = __ldg(ovcol + (wn+1)*NROW);
            n2 = __ldg(ovcol + (wn+2)*NROW);
            n3 = __ldg(ovcol + (wn+3)*NROW);
        }
        consume4(s_w, w, v0, v1, v2, v3, a0, a1);
        if (g + 1 < ng) { v0 = n0; v1 = n1; v2 = n2; v3 = n3; }
    }
    for (int w = w0 + ng*4; w < w1; w++) {   // scalar tail (<=3)
        float v = __ldg(ovcol + w*NROW);
        const float* wp = s_w + w*8;
        float4 q0 = *(const float4*)(wp    );
        float4 q1 = *(const float4*)(wp + 4);
        a0.x = fmaf(v, q0.x, a0.x); a0.y = fmaf(v, q0.y, a0.y);
        a0.z = fmaf(v, q0.z, a0.z); a0.w = fmaf(v, q0.w, a0.w);
        a1.x = fmaf(v, q1.x, a1.x); a1.y = fmaf(v, q1.y, a1.y);
        a1.z = fmaf(v, q1.z, a1.z); a1.w = fmaf(v, q1.w, a1.w);
    }

    if (ks > 0) {                            // publish partials
        float* pp = s_prt + ((ks - 1)*32 + lane)*PRTS;
        *(float4*)(pp    ) = a0;
        *(float4*)(pp + 4) = a1;
    }
    __syncthreads();

    if (t < 32) {                            // warp 0: reduce + epilogue
        #pragma unroll
        for (int s = 0; s < NKS-1; s++) {
            const float* pp = s_prt + (s*32 + lane)*PRTS;
            float4 p0 = *(const float4*)(pp);
            float4 p1 = *(const float4*)(pp + 4);
            a0.x += p0.x; a0.y += p0.y; a0.z += p0.z; a0.w += p0.w;
            a1.x += p1.x; a1.y += p1.y; a1.z += p1.z; a1.w += p1.w;
        }

        int o0 = ot*8;                       // multiple of 8 -> 32B aligned
        float4 b0 = *(const float4*)&b_lin[o0];
        float4 b1 = *(const float4*)&b_lin[o0 + 4];
        float4 r0, r1;
        r0.x = __fdividef(1.f, 1.f + __expf(-(a0.x + b0.x)));
        r0.y = __fdividef(1.f, 1.f + __expf(-(a0.y + b0.y)));
        r0.z = __fdividef(1.f, 1.f + __expf(-(a0.z + b0.z)));
        r0.w = __fdividef(1.f, 1.f + __expf(-(a0.w + b0.w)));
        r1.x = __fdividef(1.f, 1.f + __expf(-(a1.x + b1.x)));
        r1.y = __fdividef(1.f, 1.f + __expf(-(a1.y + b1.y)));
        r1.z = __fdividef(1.f, 1.f + __expf(-(a1.z + b1.z)));
        r1.w = __fdividef(1.f, 1.f + __expf(-(a1.w + b1.w)));
        *(float4*)&out_frame[row*OUTc + o0]     = r0;
        *(float4*)&out_frame[row*OUTc + o0 + 4] = r1;
    }
}

// ---------------------------------------------------------------------------
extern "C" void kernel_launch(void* const* d_in, const int* in_sizes, int n_in,
                              void* d_out, int out_size)
{
    const float* spec  = (const float*)d_in[0];
    const float* Wq    = (const float*)d_in[1];
    const float* Wk    = (const float*)d_in[2];
    const float* Wv    = (const float*)d_in[3];
    const float* rel_t = (const float*)d_in[4];
    const float* rel_f = (const float*)d_in[5];
    const float* W_lin = (const float*)d_in[6];
    const float* b_lin = (const float*)d_in[7];
    float* out = (float*)d_out;

    k1<<<NROW/4, 256>>>(spec, Wq, Wk, Wv, rel_t, rel_f, W_lin, out + FRAME_ELEMS);
    dim3 g2(NOT, NROW/32);
    k2<<<g2, 256>>>(b_lin, out);
}